// round 5
// baseline (speedup 1.0000x reference)
#include <cuda_runtime.h>
#include <math.h>

#define BATCH 256
#define DI    5120
#define RNK   160
#define NS    16
#define RX    192            // 160 (delta) + 16 (B) + 16 (C)

#define KS1   40             // split-K factor for GEMM1
#define KCH   (DI / KS1)     // 128
#define BT1   16             // batch tile GEMM1
#define WCH   16             // w prefetch chunk GEMM1

#define BT2   8              // batch tile fused kernel
#define DCH   128            // d-chunk (threads) fused kernel
#define RCH   8              // Wdt prefetch chunk fused kernel

#define LOG2E 1.4426950408889634f

// ---- scratch (no dynamic allocation allowed) ----
__device__ float g_part[KS1 * BATCH * RX];   // GEMM1 split-K partials
__device__ float g_xd[BATCH * RX];           // [xd | Bp | C]
__device__ float g_negA[NS * DI];            // transposed [n][d]: -exp(A_log)*log2e

// ---------------------------------------------------------------- prep
__global__ void k_prep(const float* __restrict__ A_log) {
    int i = blockIdx.x * blockDim.x + threadIdx.x;
    if (i < NS * DI) {
        int n = i / DI, d = i - n * DI;
        g_negA[i] = -expf(A_log[d * NS + n]) * LOG2E;
    }
}

// ---------------------------------------------------------------- GEMM1 core
// Compile-time weight stride -> LDG with immediate offsets (zero ALU per load).
template <int WSTR>
__device__ __forceinline__ void gemm1_core(const float* __restrict__ w0,
                                           const float* __restrict__ xs,
                                           float* __restrict__ acc) {
    float wbuf[2][WCH];
    const float* wp = w0;
#pragma unroll
    for (int j = 0; j < WCH; j++) wbuf[0][j] = wp[j * WSTR];

    for (int c = 0; c < KCH / WCH; c++) {
        const int cur = c & 1;
        if (c + 1 < KCH / WCH) {
            const float* wn = wp + WCH * WSTR;
#pragma unroll
            for (int j = 0; j < WCH; j++) wbuf[cur ^ 1][j] = wn[j * WSTR];
        }
#pragma unroll
        for (int j = 0; j < WCH; j++) {
            float w = wbuf[cur][j];
            const float4* xv4 = reinterpret_cast<const float4*>(xs + (c * WCH + j) * BT1);
#pragma unroll
            for (int q = 0; q < BT1 / 4; q++) {
                float4 xv = xv4[q];
                acc[4*q+0] += xv.x * w;
                acc[4*q+1] += xv.y * w;
                acc[4*q+2] += xv.z * w;
                acc[4*q+3] += xv.w * w;
            }
        }
        wp += WCH * WSTR;
    }
}

// ---------------------------------------------------------------- GEMM1
__global__ void __launch_bounds__(RX)
k_gemm1(const float* __restrict__ x,
        const float* __restrict__ Wd,
        const float* __restrict__ WB,
        const float* __restrict__ WC) {
    __shared__ float xs[KCH * BT1];         // [kk][bb]  8 KB
    const int r  = threadIdx.x;             // 0..191
    const int b0 = blockIdx.x * BT1;
    const int k0 = blockIdx.y * KCH;

    // stage x tile: x[b0+bb][k0+kk] -> xs[kk][bb]  (coalesced LDG)
    for (int i = r; i < KCH * BT1; i += RX) {
        int bb = i / KCH, kk = i - bb * KCH;
        xs[kk * BT1 + bb] = x[(b0 + bb) * DI + k0 + kk];
    }

    float acc[BT1];
#pragma unroll
    for (int i = 0; i < BT1; i++) acc[i] = 0.f;

    __syncthreads();

    if (r < 160) {
        gemm1_core<160>(Wd + r + k0 * 160, xs, acc);
    } else {
        const float* wb = (r < 176) ? (WB + (r - 160) + k0 * 16)
                                    : (WC + (r - 176) + k0 * 16);
        gemm1_core<16>(wb, xs, acc);
    }

    float* out = g_part + (blockIdx.y * BATCH + b0) * RX + r;
#pragma unroll
    for (int bb = 0; bb < BT1; bb++) out[bb * RX] = acc[bb];
}

// ---------------------------------------------------------------- reduce
__global__ void k_reduce() {
    int i = blockIdx.x * blockDim.x + threadIdx.x;    // float4 index
    if (i >= BATCH * RX / 4) return;
    const float4* p = reinterpret_cast<const float4*>(g_part) + i;
    float4 s = make_float4(0.f, 0.f, 0.f, 0.f);
#pragma unroll
    for (int ks = 0; ks < KS1; ks++) {
        float4 v = p[ks * (BATCH * RX / 4)];
        s.x += v.x; s.y += v.y; s.z += v.z; s.w += v.w;
    }
    reinterpret_cast<float4*>(g_xd)[i] = s;
}

// ---------------------------------------------------------------- fused GEMM2 + softplus + SSM
__global__ void __launch_bounds__(DCH)
k_fused(const float* __restrict__ x,
        const float* __restrict__ h,
        const float* __restrict__ Wdt,
        const float* __restrict__ b_dt,
        const float* __restrict__ Dv,
        float* __restrict__ y) {
    __shared__ float xds[RNK * BT2];        // [r][bb]  5 KB
    __shared__ float BC[BT2 * 2 * NS];      // per batch: B[16] | C[16]
    __shared__ float naS[NS * DCH];         // [n][tid]  8 KB
    __shared__ float bcs[BT2];
    const int tid = threadIdx.x;            // 0..127
    const int d   = blockIdx.x * DCH + tid;
    const int b0  = blockIdx.y * BT2;

    for (int i = tid; i < RNK * BT2; i += DCH) {
        int bb = i / RNK, r = i - bb * RNK;
        xds[r * BT2 + bb] = g_xd[(b0 + bb) * RX + r];
    }
    for (int i = tid; i < BT2 * 2 * NS; i += DCH) {
        int bb = i >> 5, j = i & 31;
        BC[i] = g_xd[(b0 + bb) * RX + 160 + j];
    }
    // stage -exp(A)*log2e rows (transposed layout: coalesced LDG, conflict-free STS/LDS)
    {
        const float* nap = g_negA + blockIdx.x * DCH + tid;
#pragma unroll
        for (int n = 0; n < NS; n++) naS[n * DCH + tid] = nap[n * DI];
    }
    __syncthreads();

    if (tid < BT2) {
        float s = 0.f;
#pragma unroll
        for (int n = 0; n < NS; n++) s += BC[tid * 32 + n] * BC[tid * 32 + NS + n];
        bcs[tid] = s;
    }

    // ---- GEMM2: acc[bb] = sum_r xd[b0+bb][r] * Wdt[r][d]
    float acc[BT2];
#pragma unroll
    for (int i = 0; i < BT2; i++) acc[i] = 0.f;

    const float* wp = Wdt + d;
    float wbuf[2][RCH];
#pragma unroll
    for (int j = 0; j < RCH; j++) wbuf[0][j] = wp[j * DI];

    for (int c = 0; c < RNK / RCH; c++) {
        const int cur = c & 1;
        if (c + 1 < RNK / RCH) {
            const float* wn = wp + RCH * DI;
#pragma unroll
            for (int j = 0; j < RCH; j++) wbuf[cur ^ 1][j] = wn[j * DI];
        }
        const int rbase = c * RCH;
#pragma unroll
        for (int j = 0; j < RCH; j++) {
            float w = wbuf[cur][j];
            const float4* xv4 = reinterpret_cast<const float4*>(xds + (rbase + j) * BT2);
            float4 x0 = xv4[0];
            float4 x1 = xv4[1];
            acc[0] += x0.x * w;  acc[1] += x0.y * w;
            acc[2] += x0.z * w;  acc[3] += x0.w * w;
            acc[4] += x1.x * w;  acc[5] += x1.y * w;
            acc[6] += x1.z * w;  acc[7] += x1.w * w;
        }
        wp += RCH * DI;
    }

    float bv = b_dt[d];
    float dt[BT2];
#pragma unroll
    for (int bb = 0; bb < BT2; bb++) {
        float z = acc[bb] + bv;
        dt[bb] = (z > 20.f) ? z : log1pf(expf(z));
    }
    float Dval = Dv[d];

    __syncthreads();   // bcs ready

    // ---- SSM readout: q outer, all batches' h loads back-to-back (MLP=BT2)
    float a2[BT2];
#pragma unroll
    for (int bb = 0; bb < BT2; bb++) a2[bb] = 0.f;

    const float4* hp = reinterpret_cast<const float4*>(h) + (b0 * DI + d) * (NS / 4);
    const int hstride4 = DI * (NS / 4);     // float4 stride between batches (imm-able)

#pragma unroll
    for (int q = 0; q < NS / 4; q++) {
        float4 hv[BT2];
#pragma unroll
        for (int bb = 0; bb < BT2; bb++) hv[bb] = hp[bb * hstride4 + q];
        float n0 = naS[(4*q+0) * DCH + tid];
        float n1 = naS[(4*q+1) * DCH + tid];
        float n2 = naS[(4*q+2) * DCH + tid];
        float n3 = naS[(4*q+3) * DCH + tid];
#pragma unroll
        for (int bb = 0; bb < BT2; bb++) {
            float4 Cq = *reinterpret_cast<const float4*>(BC + bb * 32 + NS + 4 * q);
            float dtv = dt[bb];
            a2[bb] += exp2f(dtv * n0) * hv[bb].x * Cq.x;
            a2[bb] += exp2f(dtv * n1) * hv[bb].y * Cq.y;
            a2[bb] += exp2f(dtv * n2) * hv[bb].z * Cq.z;
            a2[bb] += exp2f(dtv * n3) * hv[bb].w * Cq.w;
        }
    }

#pragma unroll
    for (int bb = 0; bb < BT2; bb++) {
        float xv = x[(b0 + bb) * DI + d];
        y[(b0 + bb) * DI + d] = a2[bb] + xv * (dt[bb] * bcs[bb] + Dval);
    }
}

// ----------------------------------------------------------------
extern "C" void kernel_launch(void* const* d_in, const int* in_sizes, int n_in,
                              void* d_out, int out_size) {
    const float* x    = (const float*)d_in[0];
    const float* h    = (const float*)d_in[1];
    const float* Wd   = (const float*)d_in[2];
    const float* Wdt  = (const float*)d_in[3];
    const float* bdt  = (const float*)d_in[4];
    const float* Alog = (const float*)d_in[5];
    const float* WB   = (const float*)d_in[6];
    const float* WC   = (const float*)d_in[7];
    const float* D    = (const float*)d_in[8];
    float* y = (float*)d_out;

    k_prep  <<<(NS * DI + 255) / 256, 256>>>(Alog);
    k_gemm1 <<<dim3(BATCH / BT1, KS1), RX>>>(x, Wd, WB, WC);
    k_reduce<<<(BATCH * RX / 4 + 255) / 256, 256>>>();
    k_fused <<<dim3(DI / DCH, BATCH / BT2), DCH>>>(x, h, Wdt, bdt, D, y);
}